// round 2
// baseline (speedup 1.0000x reference)
#include <cuda_runtime.h>
#include <math.h>

#define N_NODES 20000
#define E_EDGES 640000
#define GD 128
#define RR 8
#define KCAT (RR * GD)   // 1024

// ---------------- scratch (device globals; no allocation allowed) ----------------
__device__ float    g_agg[(size_t)N_NODES * KCAT];   // per-(dst,relation) mean accumulator, 81.9MB
__device__ float    g_cnt[N_NODES * RR];             // per-(dst,relation) edge counts
__device__ float    g_h[N_NODES * GD];               // RGCN output
__device__ float    g_q[N_NODES * GD];
__device__ float    g_k[N_NODES * GD];
__device__ float    g_v[N_NODES * GD];
__device__ float    g_e[E_EDGES];                    // per-edge score -> exp
__device__ unsigned g_smax[N_NODES];                 // encoded float max
__device__ float    g_den[N_NODES];                  // softmax denominator

// monotonic unsigned encoding of float for atomicMax
__device__ __forceinline__ unsigned enc_f(float f) {
    unsigned u = __float_as_uint(f);
    return (u & 0x80000000u) ? ~u : (u | 0x80000000u);
}
__device__ __forceinline__ float dec_f(unsigned u) {
    return (u & 0x80000000u) ? __uint_as_float(u & 0x7fffffffu) : __uint_as_float(~u);
}

// ---------------- kernels ----------------

__global__ void zero_all() {
    int i = blockIdx.x * blockDim.x + threadIdx.x;
    int stride = gridDim.x * blockDim.x;
    float4 z = make_float4(0.f, 0.f, 0.f, 0.f);
    float4* a4 = (float4*)g_agg;
    const int NA4 = N_NODES * KCAT / 4;
    for (int j = i; j < NA4; j += stride) a4[j] = z;
    for (int j = i; j < N_NODES * RR; j += stride) g_cnt[j] = 0.f;
    for (int j = i; j < N_NODES; j += stride) { g_den[j] = 0.f; g_smax[j] = 0u; }
}

__global__ void count_kernel(const int* __restrict__ ei, const int* __restrict__ et) {
    int e = blockIdx.x * blockDim.x + threadIdx.x;
    if (e >= E_EDGES) return;
    int dst = ei[E_EDGES + e];
    int r = et[e];
    atomicAdd(&g_cnt[dst * RR + r], 1.0f);
}

// warp per edge: agg[dst, r, :] += x[src, :] / max(cnt[dst,r],1)
__global__ void rgcn_scatter(const float* __restrict__ x, const int* __restrict__ ei,
                             const int* __restrict__ et) {
    int gtid = blockIdx.x * blockDim.x + threadIdx.x;
    int e = gtid >> 5, lane = gtid & 31;
    if (e >= E_EDGES) return;
    int src = ei[e], dst = ei[E_EDGES + e], r = et[e];
    float inv = 1.0f / fmaxf(g_cnt[dst * RR + r], 1.0f);
    float4 v = ((const float4*)x)[src * 32 + lane];
    float* dp = &g_agg[(size_t)dst * KCAT + r * GD + lane * 4];
    atomicAdd(dp + 0, v.x * inv);
    atomicAdd(dp + 1, v.y * inv);
    atomicAdd(dp + 2, v.z * inv);
    atomicAdd(dp + 3, v.w * inv);
}

// C[M,128] = (relu?) (A[M,K]@B[K,128] + (A2?A2[M,K2]@B2:0) + bias)
// tile: BM=64 x BN=128, BK=16, 256 threads, each thread 8x4 outputs
__global__ __launch_bounds__(256) void gemm128(
    const float* __restrict__ A, const float* __restrict__ B,
    const float* __restrict__ A2, const float* __restrict__ B2,
    const float* __restrict__ bias, float* __restrict__ C,
    int M, int K, int K2, int do_relu)
{
    __shared__ float As[16][65];
    __shared__ float Bs[16][128];
    int tid = threadIdx.x;
    int m0 = blockIdx.x * 64;
    int r = tid >> 5;        // row group 0..7 (x8 rows)
    int c = tid & 31;        // col group 0..31 (x4 cols)
    float acc[8][4];
#pragma unroll
    for (int i = 0; i < 8; ++i)
#pragma unroll
        for (int j = 0; j < 4; ++j) acc[i][j] = 0.f;

    int arow = tid >> 2;          // 0..63
    int ak   = (tid & 3) << 2;    // 0,4,8,12
    int brow = tid >> 5;          // 0..7
    int bcol = (tid & 31) << 2;   // 0..124

    for (int phase = 0; phase < 2; ++phase) {
        const float* Ap = phase ? A2 : A;
        const float* Bp = phase ? B2 : B;
        int Kp = phase ? K2 : K;
        if (Ap == nullptr) break;
        for (int k0 = 0; k0 < Kp; k0 += 16) {
            float4 av = make_float4(0.f, 0.f, 0.f, 0.f);
            if (m0 + arow < M)
                av = *(const float4*)&Ap[(size_t)(m0 + arow) * Kp + k0 + ak];
            As[ak + 0][arow] = av.x;
            As[ak + 1][arow] = av.y;
            As[ak + 2][arow] = av.z;
            As[ak + 3][arow] = av.w;
            *(float4*)&Bs[brow][bcol]     = *(const float4*)&Bp[(size_t)(k0 + brow) * GD + bcol];
            *(float4*)&Bs[brow + 8][bcol] = *(const float4*)&Bp[(size_t)(k0 + brow + 8) * GD + bcol];
            __syncthreads();
#pragma unroll
            for (int k = 0; k < 16; ++k) {
                float rA[8];
#pragma unroll
                for (int i = 0; i < 8; ++i) rA[i] = As[k][r * 8 + i];
                float4 rB = *(float4*)&Bs[k][c * 4];
#pragma unroll
                for (int i = 0; i < 8; ++i) {
                    acc[i][0] += rA[i] * rB.x;
                    acc[i][1] += rA[i] * rB.y;
                    acc[i][2] += rA[i] * rB.z;
                    acc[i][3] += rA[i] * rB.w;
                }
            }
            __syncthreads();
        }
    }

    float4 bv = *(const float4*)&bias[c * 4];
#pragma unroll
    for (int i = 0; i < 8; ++i) {
        int row = m0 + r * 8 + i;
        if (row < M) {
            float4 o;
            o.x = acc[i][0] + bv.x;
            o.y = acc[i][1] + bv.y;
            o.z = acc[i][2] + bv.z;
            o.w = acc[i][3] + bv.w;
            if (do_relu) {
                o.x = fmaxf(o.x, 0.f); o.y = fmaxf(o.y, 0.f);
                o.z = fmaxf(o.z, 0.f); o.w = fmaxf(o.w, 0.f);
            }
            *(float4*)&C[(size_t)row * GD + c * 4] = o;
        }
    }
}

// warp per edge: score = dot(q[dst], k[src]) / sqrt(128); segment max via atomicMax
__global__ void score_kernel(const int* __restrict__ ei) {
    int gtid = blockIdx.x * blockDim.x + threadIdx.x;
    int e = gtid >> 5, lane = gtid & 31;
    if (e >= E_EDGES) return;
    int src = ei[e], dst = ei[E_EDGES + e];
    float4 qv = ((const float4*)g_q)[dst * 32 + lane];
    float4 kv = ((const float4*)g_k)[src * 32 + lane];
    float p = qv.x * kv.x + qv.y * kv.y + qv.z * kv.z + qv.w * kv.w;
#pragma unroll
    for (int o = 16; o; o >>= 1) p += __shfl_xor_sync(0xffffffffu, p, o);
    if (lane == 0) {
        p *= 0.08838834764831845f;  // 1/sqrt(128)
        g_e[e] = p;
        atomicMax(&g_smax[dst], enc_f(p));
    }
}

__global__ void expsum_kernel(const int* __restrict__ ei) {
    int e = blockIdx.x * blockDim.x + threadIdx.x;
    if (e >= E_EDGES) return;
    int dst = ei[E_EDGES + e];
    float m = dec_f(g_smax[dst]);
    float ex = __expf(g_e[e] - m);
    g_e[e] = ex;
    atomicAdd(&g_den[dst], ex);
}

// warp per edge: out[dst,:] += (e/den[dst]) * v[src,:]
__global__ void scatter_v(const int* __restrict__ ei, float* __restrict__ out) {
    int gtid = blockIdx.x * blockDim.x + threadIdx.x;
    int e = gtid >> 5, lane = gtid & 31;
    if (e >= E_EDGES) return;
    int src = ei[e], dst = ei[E_EDGES + e];
    float w = g_e[e] / fmaxf(g_den[dst], 1e-16f);
    float4 vv = ((const float4*)g_v)[src * 32 + lane];
    float* op = &out[(size_t)dst * GD + lane * 4];
    atomicAdd(op + 0, vv.x * w);
    atomicAdd(op + 1, vv.y * w);
    atomicAdd(op + 2, vv.z * w);
    atomicAdd(op + 3, vv.w * w);
}

__global__ void relu_kernel(float* __restrict__ out) {
    int i = blockIdx.x * blockDim.x + threadIdx.x;
    const int n4 = N_NODES * GD / 4;
    if (i >= n4) return;
    float4 o = ((float4*)out)[i];
    o.x = fmaxf(o.x, 0.f); o.y = fmaxf(o.y, 0.f);
    o.z = fmaxf(o.z, 0.f); o.w = fmaxf(o.w, 0.f);
    ((float4*)out)[i] = o;
}

// ---------------- launch ----------------
extern "C" void kernel_launch(void* const* d_in, const int* in_sizes, int n_in,
                              void* d_out, int out_size) {
    const float* x     = (const float*)d_in[0];
    const int*   ei    = (const int*)d_in[1];   // [2,E]: src then dst
    const int*   et    = (const int*)d_in[2];
    const float* rw    = (const float*)d_in[3]; // [R,G,H1] == [1024,128]
    const float* rroot = (const float*)d_in[4];
    const float* rbias = (const float*)d_in[5];
    const float* Wq    = (const float*)d_in[6];
    const float* bq    = (const float*)d_in[7];
    const float* Wk    = (const float*)d_in[8];
    const float* bk    = (const float*)d_in[9];
    const float* Wv    = (const float*)d_in[10];
    const float* bv    = (const float*)d_in[11];
    const float* Ws    = (const float*)d_in[12];
    const float* bs    = (const float*)d_in[13];
    float* out = (float*)d_out;

    const int threads = 256;
    const int eBlocks  = (E_EDGES + threads - 1) / threads;       // 2500
    const int ewBlocks = (E_EDGES * 32 + threads - 1) / threads;  // 80000
    const int mBlocks  = (N_NODES + 63) / 64;                     // 313
    const int rBlocks  = (N_NODES * GD / 4 + threads - 1) / threads;

    // get symbol addresses for scratch passed as kernel args where needed
    float* d_h; cudaGetSymbolAddress((void**)&d_h, g_h);
    float* d_q; cudaGetSymbolAddress((void**)&d_q, g_q);
    float* d_k; cudaGetSymbolAddress((void**)&d_k, g_k);
    float* d_v; cudaGetSymbolAddress((void**)&d_v, g_v);
    float* d_agg; cudaGetSymbolAddress((void**)&d_agg, g_agg);

    zero_all<<<1184, threads>>>();
    count_kernel<<<eBlocks, threads>>>(ei, et);
    rgcn_scatter<<<ewBlocks, threads>>>(x, ei, et);
    // h = relu(agg @ Wcat + x @ root + bias)
    gemm128<<<mBlocks, threads>>>(d_agg, rw, x, rroot, rbias, d_h,
                                  N_NODES, KCAT, GD, 1);
    // q, k, v, skip(->out)
    gemm128<<<mBlocks, threads>>>(d_h, Wq, nullptr, nullptr, bq, d_q, N_NODES, GD, 0, 0);
    gemm128<<<mBlocks, threads>>>(d_h, Wk, nullptr, nullptr, bk, d_k, N_NODES, GD, 0, 0);
    gemm128<<<mBlocks, threads>>>(d_h, Wv, nullptr, nullptr, bv, d_v, N_NODES, GD, 0, 0);
    gemm128<<<mBlocks, threads>>>(d_h, Ws, nullptr, nullptr, bs, out, N_NODES, GD, 0, 0);

    score_kernel<<<ewBlocks, threads>>>(ei);
    expsum_kernel<<<eBlocks, threads>>>(ei);
    scatter_v<<<ewBlocks, threads>>>(ei, out);
    relu_kernel<<<rBlocks, threads>>>(out);
}

// round 7
// speedup vs baseline: 1.4180x; 1.4180x over previous
#include <cuda_runtime.h>
#include <math.h>

#define N_NODES 20000
#define E_EDGES 640000
#define GD 128
#define RR 8
#define KCAT (RR * GD)   // 1024

// ---------------- scratch (device globals) ----------------
__device__ float g_agg[(size_t)N_NODES * KCAT];   // per-(dst,relation) mean accumulator
__device__ int   g_cnt[N_NODES * RR];             // per-(dst,relation) edge counts
__device__ int   g_deg[N_NODES];                  // in-degree per dst
__device__ int   g_off[N_NODES + 1];              // CSR offsets
__device__ int   g_cur[N_NODES];                  // scatter cursors
__device__ int   g_pk[E_EDGES];                   // packed src | (r<<16), CSR order
__device__ float g_h[N_NODES * GD];               // RGCN output
__device__ float g_q[N_NODES * GD];
__device__ float g_k[N_NODES * GD];
__device__ float g_v[N_NODES * GD];

// ---------------- CSR build ----------------

__global__ void zero_ints() {
    int i = blockIdx.x * blockDim.x + threadIdx.x;
    int stride = gridDim.x * blockDim.x;
    for (int j = i; j < N_NODES * RR; j += stride) g_cnt[j] = 0;
    for (int j = i; j < N_NODES; j += stride) { g_deg[j] = 0; g_cur[j] = 0; }
}

__global__ void count_kernel(const int* __restrict__ ei, const int* __restrict__ et) {
    int e = blockIdx.x * blockDim.x + threadIdx.x;
    if (e >= E_EDGES) return;
    int dst = ei[E_EDGES + e];
    int r = et[e];
    atomicAdd(&g_deg[dst], 1);
    atomicAdd(&g_cnt[dst * RR + r], 1);
}

// single-block exclusive scan over g_deg -> g_off
__global__ void scan_kernel() {
    __shared__ int s[1024];
    __shared__ int carry;
    int tid = threadIdx.x;
    if (tid == 0) { carry = 0; g_off[0] = 0; }
    __syncthreads();
    for (int base = 0; base < N_NODES; base += 1024) {
        int v = (base + tid < N_NODES) ? g_deg[base + tid] : 0;
        s[tid] = v;
        __syncthreads();
        // Kogge-Stone inclusive scan
        for (int o = 1; o < 1024; o <<= 1) {
            int t = (tid >= o) ? s[tid - o] : 0;
            __syncthreads();
            s[tid] += t;
            __syncthreads();
        }
        if (base + tid < N_NODES) g_off[base + tid + 1] = s[tid] + carry;
        __syncthreads();
        if (tid == 0) {
            int last = (N_NODES - base >= 1024) ? 1023 : (N_NODES - base - 1);
            carry += s[last];
        }
        __syncthreads();
    }
}

__global__ void scatter_kernel(const int* __restrict__ ei, const int* __restrict__ et) {
    int e = blockIdx.x * blockDim.x + threadIdx.x;
    if (e >= E_EDGES) return;
    int src = ei[e], dst = ei[E_EDGES + e], r = et[e];
    int pos = atomicAdd(&g_cur[dst], 1);
    g_pk[g_off[dst] + pos] = src | (r << 16);
}

// ---------------- RGCN aggregation: block per dst, no atomics ----------------
// agg[dst, r, t] = sum_{e in dst, rel r} x[src_e, t] / max(cnt[dst,r],1)
__global__ __launch_bounds__(128) void rgcn_agg(const float* __restrict__ x) {
    __shared__ float inv_s[RR];
    __shared__ int epk[128];
    int dst = blockIdx.x;
    int t = threadIdx.x;
    if (t < RR) {
        int c = g_cnt[dst * RR + t];
        inv_s[t] = 1.0f / (float)max(c, 1);
    }
    float acc[RR];
#pragma unroll
    for (int rr = 0; rr < RR; ++rr) acc[rr] = 0.f;
    int beg = g_off[dst], end = g_off[dst + 1];
    __syncthreads();
    for (int base = beg; base < end; base += 128) {
        int n = min(128, end - base);
        if (t < n) epk[t] = g_pk[base + t];
        __syncthreads();
#pragma unroll 4
        for (int j = 0; j < n; ++j) {
            int p = epk[j];
            int src = p & 0xFFFF;
            int r = p >> 16;
            float w = x[src * GD + t] * inv_s[r];
#pragma unroll
            for (int rr = 0; rr < RR; ++rr) acc[rr] += (rr == r) ? w : 0.f;
        }
        __syncthreads();
    }
    float* ap = &g_agg[(size_t)dst * KCAT + t];
#pragma unroll
    for (int rr = 0; rr < RR; ++rr) ap[rr * GD] = acc[rr];
}

// ---------------- GEMM (fp32 SIMT, near peak) ----------------
// C[M,128] = (relu?) (A[M,K]@B[K,128] + (A2?A2[M,K2]@B2:0) + bias)
__global__ __launch_bounds__(256) void gemm128(
    const float* __restrict__ A, const float* __restrict__ B,
    const float* __restrict__ A2, const float* __restrict__ B2,
    const float* __restrict__ bias, float* __restrict__ C,
    int M, int K, int K2, int do_relu)
{
    __shared__ float As[16][65];
    __shared__ float Bs[16][128];
    int tid = threadIdx.x;
    int m0 = blockIdx.x * 64;
    int r = tid >> 5;
    int c = tid & 31;
    float acc[8][4];
#pragma unroll
    for (int i = 0; i < 8; ++i)
#pragma unroll
        for (int j = 0; j < 4; ++j) acc[i][j] = 0.f;

    int arow = tid >> 2;
    int ak   = (tid & 3) << 2;
    int brow = tid >> 5;
    int bcol = (tid & 31) << 2;

    for (int phase = 0; phase < 2; ++phase) {
        const float* Ap = phase ? A2 : A;
        const float* Bp = phase ? B2 : B;
        int Kp = phase ? K2 : K;
        if (Ap == nullptr) break;
        for (int k0 = 0; k0 < Kp; k0 += 16) {
            float4 av = make_float4(0.f, 0.f, 0.f, 0.f);
            if (m0 + arow < M)
                av = *(const float4*)&Ap[(size_t)(m0 + arow) * Kp + k0 + ak];
            As[ak + 0][arow] = av.x;
            As[ak + 1][arow] = av.y;
            As[ak + 2][arow] = av.z;
            As[ak + 3][arow] = av.w;
            *(float4*)&Bs[brow][bcol]     = *(const float4*)&Bp[(size_t)(k0 + brow) * GD + bcol];
            *(float4*)&Bs[brow + 8][bcol] = *(const float4*)&Bp[(size_t)(k0 + brow + 8) * GD + bcol];
            __syncthreads();
#pragma unroll
            for (int k = 0; k < 16; ++k) {
                float rA[8];
#pragma unroll
                for (int i = 0; i < 8; ++i) rA[i] = As[k][r * 8 + i];
                float4 rB = *(float4*)&Bs[k][c * 4];
#pragma unroll
                for (int i = 0; i < 8; ++i) {
                    acc[i][0] += rA[i] * rB.x;
                    acc[i][1] += rA[i] * rB.y;
                    acc[i][2] += rA[i] * rB.z;
                    acc[i][3] += rA[i] * rB.w;
                }
            }
            __syncthreads();
        }
    }

    float4 bv = *(const float4*)&bias[c * 4];
#pragma unroll
    for (int i = 0; i < 8; ++i) {
        int row = m0 + r * 8 + i;
        if (row < M) {
            float4 o;
            o.x = acc[i][0] + bv.x;
            o.y = acc[i][1] + bv.y;
            o.z = acc[i][2] + bv.z;
            o.w = acc[i][3] + bv.w;
            if (do_relu) {
                o.x = fmaxf(o.x, 0.f); o.y = fmaxf(o.y, 0.f);
                o.z = fmaxf(o.z, 0.f); o.w = fmaxf(o.w, 0.f);
            }
            *(float4*)&C[(size_t)row * GD + c * 4] = o;
        }
    }
}

// ---------------- fused attention: block per dst, online softmax ----------------
__global__ __launch_bounds__(128) void attn_kernel(float* __restrict__ out) {
    __shared__ float qs[GD];
    __shared__ int epk[128];
    __shared__ float wm[4], ws[4];
    __shared__ float wacc[4][GD];
    int dst = blockIdx.x;
    int t = threadIdx.x;
    int w = t >> 5, lane = t & 31;

    qs[t] = g_q[dst * GD + t];
    int beg = g_off[dst], end = g_off[dst + 1];
    __syncthreads();
    float4 qv = ((float4*)qs)[lane];

    const float4* k4 = (const float4*)g_k;
    const float4* v4 = (const float4*)g_v;

    float m = -INFINITY, s = 0.f;
    float4 acc = make_float4(0.f, 0.f, 0.f, 0.f);

    for (int base = beg; base < end; base += 128) {
        int n = min(128, end - base);
        if (t < n) epk[t] = g_pk[base + t];
        __syncthreads();
        for (int j = w; j < n; j += 4) {
            int src = epk[j] & 0xFFFF;
            float4 kv = k4[src * 32 + lane];
            float p = qv.x * kv.x + qv.y * kv.y + qv.z * kv.z + qv.w * kv.w;
#pragma unroll
            for (int o = 16; o; o >>= 1) p += __shfl_xor_sync(0xffffffffu, p, o);
            p *= 0.08838834764831845f;  // 1/sqrt(128)
            float4 vv = v4[src * 32 + lane];
            float mn = fmaxf(m, p);
            float scale = __expf(m - mn);   // m=-inf -> 0
            float pe = __expf(p - mn);
            s = s * scale + pe;
            acc.x = acc.x * scale + pe * vv.x;
            acc.y = acc.y * scale + pe * vv.y;
            acc.z = acc.z * scale + pe * vv.z;
            acc.w = acc.w * scale + pe * vv.w;
            m = mn;
        }
        __syncthreads();
    }

    if (lane == 0) { wm[w] = m; ws[w] = s; }
    ((float4*)wacc[w])[lane] = acc;
    __syncthreads();

    float M = fmaxf(fmaxf(wm[0], wm[1]), fmaxf(wm[2], wm[3]));
    float stot = 0.f, val = 0.f;
#pragma unroll
    for (int w2 = 0; w2 < 4; ++w2) {
        float sw = ws[w2];
        if (sw > 0.f) {
            float sc = __expf(wm[w2] - M);
            stot += sw * sc;
            val += wacc[w2][t] * sc;
        }
    }
    float res = (stot > 0.f) ? (val / stot) : 0.f;
    float o = out[dst * GD + t] + res;
    out[dst * GD + t] = fmaxf(o, 0.f);
}

// ---------------- launch ----------------
extern "C" void kernel_launch(void* const* d_in, const int* in_sizes, int n_in,
                              void* d_out, int out_size) {
    const float* x     = (const float*)d_in[0];
    const int*   ei    = (const int*)d_in[1];
    const int*   et    = (const int*)d_in[2];
    const float* rw    = (const float*)d_in[3];
    const float* rroot = (const float*)d_in[4];
    const float* rbias = (const float*)d_in[5];
    const float* Wq    = (const float*)d_in[6];
    const float* bq    = (const float*)d_in[7];
    const float* Wk    = (const float*)d_in[8];
    const float* bk    = (const float*)d_in[9];
    const float* Wv    = (const float*)d_in[10];
    const float* bv    = (const float*)d_in[11];
    const float* Ws    = (const float*)d_in[12];
    const float* bs    = (const float*)d_in[13];
    float* out = (float*)d_out;

    const int threads = 256;
    const int eBlocks = (E_EDGES + threads - 1) / threads;
    const int mBlocks = (N_NODES + 63) / 64;

    float* d_h; cudaGetSymbolAddress((void**)&d_h, g_h);
    float* d_q; cudaGetSymbolAddress((void**)&d_q, g_q);
    float* d_k; cudaGetSymbolAddress((void**)&d_k, g_k);
    float* d_v; cudaGetSymbolAddress((void**)&d_v, g_v);
    float* d_agg; cudaGetSymbolAddress((void**)&d_agg, g_agg);

    // CSR build
    zero_ints<<<160, threads>>>();
    count_kernel<<<eBlocks, threads>>>(ei, et);
    scan_kernel<<<1, 1024>>>();
    scatter_kernel<<<eBlocks, threads>>>(ei, et);

    // RGCN: aggregate (no atomics, writes full agg), then fused GEMM + relu
    rgcn_agg<<<N_NODES, 128>>>(x);
    gemm128<<<mBlocks, threads>>>(d_agg, rw, x, rroot, rbias, d_h,
                                  N_NODES, KCAT, GD, 1);

    // q, k, v, skip(->out)
    gemm128<<<mBlocks, threads>>>(d_h, Wq, nullptr, nullptr, bq, d_q, N_NODES, GD, 0, 0);
    gemm128<<<mBlocks, threads>>>(d_h, Wk, nullptr, nullptr, bk, d_k, N_NODES, GD, 0, 0);
    gemm128<<<mBlocks, threads>>>(d_h, Wv, nullptr, nullptr, bv, d_v, N_NODES, GD, 0, 0);
    gemm128<<<mBlocks, threads>>>(d_h, Ws, nullptr, nullptr, bs, out, N_NODES, GD, 0, 0);

    // fused attention + skip + relu
    attn_kernel<<<N_NODES, 128>>>(out);
}

// round 9
// speedup vs baseline: 1.8028x; 1.2713x over previous
#include <cuda_runtime.h>
#include <math.h>
#include <stdint.h>

#define N_NODES 20000
#define E_EDGES 640000
#define GD 128
#define RR 8
#define KCAT (RR * GD)   // 1024

// ---------------- scratch (device globals) ----------------
__device__ float g_agg[(size_t)N_NODES * KCAT];
__device__ int   g_cnt[N_NODES * RR];
__device__ int   g_deg[N_NODES];
__device__ int   g_off[N_NODES + 1];
__device__ int   g_cur[N_NODES];
__device__ int   g_pk[E_EDGES];                   // packed src | (r<<16)
__device__ float g_h[N_NODES * GD];
__device__ float g_q[N_NODES * GD];
__device__ float g_k[N_NODES * GD];
__device__ float g_v[N_NODES * GD];

// ---------------- CSR build ----------------

__global__ void zero_ints() {
    int i = blockIdx.x * blockDim.x + threadIdx.x;
    int stride = gridDim.x * blockDim.x;
    for (int j = i; j < N_NODES * RR; j += stride) g_cnt[j] = 0;
    for (int j = i; j < N_NODES; j += stride) { g_deg[j] = 0; g_cur[j] = 0; }
}

__global__ void count_kernel(const int* __restrict__ ei, const int* __restrict__ et) {
    int e = blockIdx.x * blockDim.x + threadIdx.x;
    if (e >= E_EDGES) return;
    int dst = ei[E_EDGES + e];
    int r = et[e];
    atomicAdd(&g_deg[dst], 1);
    atomicAdd(&g_cnt[dst * RR + r], 1);
}

__global__ void scan_kernel() {
    __shared__ int s[1024];
    __shared__ int carry;
    int tid = threadIdx.x;
    if (tid == 0) { carry = 0; g_off[0] = 0; }
    __syncthreads();
    for (int base = 0; base < N_NODES; base += 1024) {
        int v = (base + tid < N_NODES) ? g_deg[base + tid] : 0;
        s[tid] = v;
        __syncthreads();
        for (int o = 1; o < 1024; o <<= 1) {
            int t = (tid >= o) ? s[tid - o] : 0;
            __syncthreads();
            s[tid] += t;
            __syncthreads();
        }
        if (base + tid < N_NODES) g_off[base + tid + 1] = s[tid] + carry;
        __syncthreads();
        if (tid == 0) {
            int last = (N_NODES - base >= 1024) ? 1023 : (N_NODES - base - 1);
            carry += s[last];
        }
        __syncthreads();
    }
}

__global__ void scatter_kernel(const int* __restrict__ ei, const int* __restrict__ et) {
    int e = blockIdx.x * blockDim.x + threadIdx.x;
    if (e >= E_EDGES) return;
    int src = ei[e], dst = ei[E_EDGES + e], r = et[e];
    int pos = atomicAdd(&g_cur[dst], 1);
    g_pk[g_off[dst] + pos] = src | (r << 16);
}

// ---------------- RGCN aggregation: block per dst ----------------
__global__ __launch_bounds__(128) void rgcn_agg(const float* __restrict__ x) {
    __shared__ float inv_s[RR];
    __shared__ int epk[128];
    int dst = blockIdx.x;
    int t = threadIdx.x;
    if (t < RR) {
        int c = g_cnt[dst * RR + t];
        inv_s[t] = 1.0f / (float)max(c, 1);
    }
    float acc[RR];
#pragma unroll
    for (int rr = 0; rr < RR; ++rr) acc[rr] = 0.f;
    int beg = g_off[dst], end = g_off[dst + 1];
    __syncthreads();
    for (int base = beg; base < end; base += 128) {
        int n = min(128, end - base);
        if (t < n) epk[t] = g_pk[base + t];
        __syncthreads();
#pragma unroll 4
        for (int j = 0; j < n; ++j) {
            int p = epk[j];
            int src = p & 0xFFFF;
            int r = p >> 16;
            float w = x[src * GD + t] * inv_s[r];
#pragma unroll
            for (int rr = 0; rr < RR; ++rr) acc[rr] += (rr == r) ? w : 0.f;
        }
        __syncthreads();
    }
    float* ap = &g_agg[(size_t)dst * KCAT + t];
#pragma unroll
    for (int rr = 0; rr < RR; ++rr) ap[rr * GD] = acc[rr];
}

// ---------------- tf32 tensor-core GEMM ----------------
// C[M,128] = (relu?)(A[M,K]@B[K,128] + (A2? A2[M,K2]@B2 : 0) + bias)
// BM=128, BN=128, BK=16; 256 threads = 8 warps (4x2), warp tile 32x64,
// mma.sync m16n8k8 tf32, fp32 accumulate.

__device__ __forceinline__ uint32_t f2tf32(float f) {
    uint32_t r;
    asm("cvt.rna.tf32.f32 %0, %1;" : "=r"(r) : "f"(f));
    return r;
}

__global__ __launch_bounds__(256) void gemm_tf32(
    const float* __restrict__ A, const float* __restrict__ B,
    const float* __restrict__ A2, const float* __restrict__ B2,
    const float* __restrict__ bias, float* __restrict__ C,
    int M, int K, int K2, int do_relu)
{
    __shared__ uint32_t As[128][20];   // [row][k], pad 16->20: conflict-free frag reads
    __shared__ uint32_t Bs[16][132];   // [k][n], pad 128->132

    int tid = threadIdx.x;
    int m0 = blockIdx.x * 128;
    int warp = tid >> 5, lane = tid & 31;
    int wm = warp >> 1, wn = warp & 1;       // 4 x 2 warps
    int grp = lane >> 2, tig = lane & 3;     // mma fragment coords

    float c[2][8][4];
#pragma unroll
    for (int mi = 0; mi < 2; ++mi)
#pragma unroll
        for (int ni = 0; ni < 8; ++ni)
#pragma unroll
            for (int j = 0; j < 4; ++j) c[mi][ni][j] = 0.f;

    // global-load index mapping
    int a_row = tid >> 1;               // 0..127
    int a_kc  = (tid & 1) << 3;         // 0 or 8 (two float4 per row half)
    int b_row0 = tid >> 5;              // 0..7
    int b_col = (tid & 31) << 2;        // 0..124

    for (int phase = 0; phase < 2; ++phase) {
        const float* Ap = phase ? A2 : A;
        const float* Bp = phase ? B2 : B;
        int Kp = phase ? K2 : K;
        if (Ap == nullptr) break;
        for (int k0 = 0; k0 < Kp; k0 += 16) {
            // load A tile 128x16 (each thread: 2 float4 in one row)
            {
                float4 v0 = make_float4(0.f,0.f,0.f,0.f);
                float4 v1 = v0;
                if (m0 + a_row < M) {
                    const float* ap = &Ap[(size_t)(m0 + a_row) * Kp + k0 + a_kc];
                    v0 = *(const float4*)ap;
                    v1 = *(const float4*)(ap + 4);
                }
                As[a_row][a_kc + 0] = f2tf32(v0.x);
                As[a_row][a_kc + 1] = f2tf32(v0.y);
                As[a_row][a_kc + 2] = f2tf32(v0.z);
                As[a_row][a_kc + 3] = f2tf32(v0.w);
                As[a_row][a_kc + 4] = f2tf32(v1.x);
                As[a_row][a_kc + 5] = f2tf32(v1.y);
                As[a_row][a_kc + 6] = f2tf32(v1.z);
                As[a_row][a_kc + 7] = f2tf32(v1.w);
            }
            // load B tile 16x128 (each thread: 2 float4)
            {
                float4 v0 = *(const float4*)&Bp[(size_t)(k0 + b_row0) * GD + b_col];
                float4 v1 = *(const float4*)&Bp[(size_t)(k0 + b_row0 + 8) * GD + b_col];
                Bs[b_row0][b_col + 0] = f2tf32(v0.x);
                Bs[b_row0][b_col + 1] = f2tf32(v0.y);
                Bs[b_row0][b_col + 2] = f2tf32(v0.z);
                Bs[b_row0][b_col + 3] = f2tf32(v0.w);
                Bs[b_row0 + 8][b_col + 0] = f2tf32(v1.x);
                Bs[b_row0 + 8][b_col + 1] = f2tf32(v1.y);
                Bs[b_row0 + 8][b_col + 2] = f2tf32(v1.z);
                Bs[b_row0 + 8][b_col + 3] = f2tf32(v1.w);
            }
            __syncthreads();

#pragma unroll
            for (int ks = 0; ks < 2; ++ks) {
                int kk = ks << 3;
                uint32_t a[2][4];
#pragma unroll
                for (int mi = 0; mi < 2; ++mi) {
                    int r0 = wm * 32 + mi * 16 + grp;
                    a[mi][0] = As[r0][kk + tig];
                    a[mi][1] = As[r0 + 8][kk + tig];
                    a[mi][2] = As[r0][kk + tig + 4];
                    a[mi][3] = As[r0 + 8][kk + tig + 4];
                }
                uint32_t b[8][2];
#pragma unroll
                for (int ni = 0; ni < 8; ++ni) {
                    int n = wn * 64 + ni * 8 + grp;
                    b[ni][0] = Bs[kk + tig][n];
                    b[ni][1] = Bs[kk + tig + 4][n];
                }
#pragma unroll
                for (int mi = 0; mi < 2; ++mi)
#pragma unroll
                    for (int ni = 0; ni < 8; ++ni) {
                        asm volatile(
                            "mma.sync.aligned.m16n8k8.row.col.f32.tf32.tf32.f32 "
                            "{%0,%1,%2,%3}, {%4,%5,%6,%7}, {%8,%9}, {%0,%1,%2,%3};"
                            : "+f"(c[mi][ni][0]), "+f"(c[mi][ni][1]),
                              "+f"(c[mi][ni][2]), "+f"(c[mi][ni][3])
                            : "r"(a[mi][0]), "r"(a[mi][1]), "r"(a[mi][2]), "r"(a[mi][3]),
                              "r"(b[ni][0]), "r"(b[ni][1]));
                    }
            }
            __syncthreads();
        }
    }

    // epilogue: bias + optional relu, float2 stores
#pragma unroll
    for (int mi = 0; mi < 2; ++mi) {
        int rbase = m0 + wm * 32 + mi * 16 + grp;
#pragma unroll
        for (int ni = 0; ni < 8; ++ni) {
            int col = wn * 64 + ni * 8 + 2 * tig;
            float2 bv = *(const float2*)&bias[col];
            if (rbase < M) {
                float2 o;
                o.x = c[mi][ni][0] + bv.x;
                o.y = c[mi][ni][1] + bv.y;
                if (do_relu) { o.x = fmaxf(o.x, 0.f); o.y = fmaxf(o.y, 0.f); }
                *(float2*)&C[(size_t)rbase * GD + col] = o;
            }
            if (rbase + 8 < M) {
                float2 o;
                o.x = c[mi][ni][2] + bv.x;
                o.y = c[mi][ni][3] + bv.y;
                if (do_relu) { o.x = fmaxf(o.x, 0.f); o.y = fmaxf(o.y, 0.f); }
                *(float2*)&C[(size_t)(rbase + 8) * GD + col] = o;
            }
        }
    }
}

// ---------------- fused attention: block per dst, online softmax ----------------
__global__ __launch_bounds__(128) void attn_kernel(float* __restrict__ out) {
    __shared__ float qs[GD];
    __shared__ int epk[128];
    __shared__ float wm[4], ws[4];
    __shared__ float wacc[4][GD];
    int dst = blockIdx.x;
    int t = threadIdx.x;
    int w = t >> 5, lane = t & 31;

    qs[t] = g_q[dst * GD + t];
    int beg = g_off[dst], end = g_off[dst + 1];
    __syncthreads();
    float4 qv = ((float4*)qs)[lane];

    const float4* k4 = (const float4*)g_k;
    const float4* v4 = (const float4*)g_v;

    float m = -INFINITY, s = 0.f;
    float4 acc = make_float4(0.f, 0.f, 0.f, 0.f);

    for (int base = beg; base < end; base += 128) {
        int n = min(128, end - base);
        if (t < n) epk[t] = g_pk[base + t];
        __syncthreads();
        for (int j = w; j < n; j += 4) {
            int src = epk[j] & 0xFFFF;
            float4 kv = k4[src * 32 + lane];
            float p = qv.x * kv.x + qv.y * kv.y + qv.z * kv.z + qv.w * kv.w;
#pragma unroll
            for (int o = 16; o; o >>= 1) p += __shfl_xor_sync(0xffffffffu, p, o);
            p *= 0.08838834764831845f;  // 1/sqrt(128)
            float4 vv = v4[src * 32 + lane];
            float mn = fmaxf(m, p);
            float scale = __expf(m - mn);
            float pe = __expf(p - mn);
            s = s * scale + pe;
            acc.x = acc.x * scale + pe * vv.x;
            acc.y = acc.y * scale + pe * vv.y;
            acc.z = acc.z * scale + pe * vv.z;
            acc.w = acc.w * scale + pe * vv.w;
            m = mn;
        }
        __syncthreads();
    }

    if (lane == 0) { wm[w] = m; ws[w] = s; }
    ((float4*)wacc[w])[lane] = acc;
    __syncthreads();

    float M = fmaxf(fmaxf(wm[0], wm[1]), fmaxf(wm[2], wm[3]));
    float stot = 0.f, val = 0.f;
#pragma unroll
    for (int w2 = 0; w2 < 4; ++w2) {
        float sw = ws[w2];
        if (sw > 0.f) {
            float sc = __expf(wm[w2] - M);
            stot += sw * sc;
            val += wacc[w2][t] * sc;
        }
    }
    float res = (stot > 0.f) ? (val / stot) : 0.f;
    float o = out[dst * GD + t] + res;
    out[dst * GD + t] = fmaxf(o, 0.f);
}

// ---------------- launch ----------------
extern "C" void kernel_launch(void* const* d_in, const int* in_sizes, int n_in,
                              void* d_out, int out_size) {
    const float* x     = (const float*)d_in[0];
    const int*   ei    = (const int*)d_in[1];
    const int*   et    = (const int*)d_in[2];
    const float* rw    = (const float*)d_in[3];
    const float* rroot = (const float*)d_in[4];
    const float* rbias = (const float*)d_in[5];
    const float* Wq    = (const float*)d_in[6];
    const float* bq    = (const float*)d_in[7];
    const float* Wk    = (const float*)d_in[8];
    const float* bk    = (const float*)d_in[9];
    const float* Wv    = (const float*)d_in[10];
    const float* bv    = (const float*)d_in[11];
    const float* Ws    = (const float*)d_in[12];
    const float* bs    = (const float*)d_in[13];
    float* out = (float*)d_out;

    const int threads = 256;
    const int eBlocks = (E_EDGES + threads - 1) / threads;
    const int mBlocks = (N_NODES + 127) / 128;   // 157

    float* d_h; cudaGetSymbolAddress((void**)&d_h, g_h);
    float* d_q; cudaGetSymbolAddress((void**)&d_q, g_q);
    float* d_k; cudaGetSymbolAddress((void**)&d_k, g_k);
    float* d_v; cudaGetSymbolAddress((void**)&d_v, g_v);
    float* d_agg; cudaGetSymbolAddress((void**)&d_agg, g_agg);

    // CSR build
    zero_ints<<<160, threads>>>();
    count_kernel<<<eBlocks, threads>>>(ei, et);
    scan_kernel<<<1, 1024>>>();
    scatter_kernel<<<eBlocks, threads>>>(ei, et);

    // RGCN
    rgcn_agg<<<N_NODES, 128>>>(x);
    gemm_tf32<<<mBlocks, threads>>>(d_agg, rw, x, rroot, rbias, d_h,
                                    N_NODES, KCAT, GD, 1);

    // q, k, v, skip(->out)
    gemm_tf32<<<mBlocks, threads>>>(d_h, Wq, nullptr, nullptr, bq, d_q, N_NODES, GD, 0, 0);
    gemm_tf32<<<mBlocks, threads>>>(d_h, Wk, nullptr, nullptr, bk, d_k, N_NODES, GD, 0, 0);
    gemm_tf32<<<mBlocks, threads>>>(d_h, Wv, nullptr, nullptr, bv, d_v, N_NODES, GD, 0, 0);
    gemm_tf32<<<mBlocks, threads>>>(d_h, Ws, nullptr, nullptr, bs, out, N_NODES, GD, 0, 0);

    // fused attention + skip + relu
    attn_kernel<<<N_NODES, 128>>>(out);
}

// round 10
// speedup vs baseline: 2.1494x; 1.1923x over previous
#include <cuda_runtime.h>
#include <math.h>
#include <stdint.h>

#define N_NODES 20000
#define E_EDGES 640000
#define GD 128
#define RR 8
#define KCAT (RR * GD)   // 1024

// ---------------- scratch (device globals) ----------------
__device__ float g_agg[(size_t)N_NODES * KCAT];
__device__ int   g_cnt[N_NODES * RR];
__device__ int   g_deg[N_NODES];
__device__ int   g_off[N_NODES + 1];
__device__ int   g_cur[N_NODES];
__device__ int   g_pk[E_EDGES];                   // packed src | (r<<16)
__device__ float g_h[N_NODES * GD];
__device__ float g_q[N_NODES * GD];
__device__ float g_k[N_NODES * GD];
__device__ float g_v[N_NODES * GD];

// ---------------- CSR build ----------------

__global__ void zero_ints() {
    int i = blockIdx.x * blockDim.x + threadIdx.x;
    int stride = gridDim.x * blockDim.x;
    for (int j = i; j < N_NODES * RR; j += stride) g_cnt[j] = 0;
    for (int j = i; j < N_NODES; j += stride) { g_deg[j] = 0; g_cur[j] = 0; }
}

// 4 independent edges per thread for MLP
__global__ void count_kernel(const int* __restrict__ ei, const int* __restrict__ et) {
    int i = blockIdx.x * blockDim.x + threadIdx.x;
    const int Q = E_EDGES / 4;
    if (i >= Q) return;
#pragma unroll
    for (int u = 0; u < 4; ++u) {
        int e = i + u * Q;
        int dst = ei[E_EDGES + e];
        int r = et[e];
        atomicAdd(&g_deg[dst], 1);
        atomicAdd(&g_cnt[dst * RR + r], 1);
    }
}

// single block, 1024 threads, per-thread chunk + 2-level warp scan
__global__ __launch_bounds__(1024) void scan_kernel() {
    __shared__ int warp_sums[32];
    int tid = threadIdx.x;
    const int CHUNK = (N_NODES + 1023) / 1024;   // 20
    int start = tid * CHUNK;
    int end = min(start + CHUNK, N_NODES);
    int sum = 0;
    for (int i = start; i < end; ++i) sum += g_deg[i];
    int lane = tid & 31, warp = tid >> 5;
    int v = sum;
#pragma unroll
    for (int o = 1; o < 32; o <<= 1) {
        int u = __shfl_up_sync(0xffffffffu, v, o);
        if (lane >= o) v += u;
    }
    if (lane == 31) warp_sums[warp] = v;
    __syncthreads();
    if (warp == 0) {
        int w = warp_sums[lane];
#pragma unroll
        for (int o = 1; o < 32; o <<= 1) {
            int u = __shfl_up_sync(0xffffffffu, w, o);
            if (lane >= o) w += u;
        }
        warp_sums[lane] = w;
    }
    __syncthreads();
    int excl = v - sum + (warp ? warp_sums[warp - 1] : 0);
    int run = excl;
    for (int i = start; i < end; ++i) { g_off[i] = run; run += g_deg[i]; }
    if (tid == 1023) g_off[N_NODES] = run;   // empty chunk -> run == total
}

__global__ void scatter_kernel(const int* __restrict__ ei, const int* __restrict__ et) {
    int i = blockIdx.x * blockDim.x + threadIdx.x;
    const int Q = E_EDGES / 4;
    if (i >= Q) return;
#pragma unroll
    for (int u = 0; u < 4; ++u) {
        int e = i + u * Q;
        int src = ei[e], dst = ei[E_EDGES + e], r = et[e];
        int pos = atomicAdd(&g_cur[dst], 1);
        g_pk[g_off[dst] + pos] = src | (r << 16);
    }
}

// ---------------- RGCN aggregation: block per dst ----------------
__global__ __launch_bounds__(128) void rgcn_agg(const float* __restrict__ x) {
    __shared__ float inv_s[RR];
    __shared__ int epk[128];
    int dst = blockIdx.x;
    int t = threadIdx.x;
    if (t < RR) {
        int c = g_cnt[dst * RR + t];
        inv_s[t] = 1.0f / (float)max(c, 1);
    }
    float acc[RR];
#pragma unroll
    for (int rr = 0; rr < RR; ++rr) acc[rr] = 0.f;
    int beg = g_off[dst], end = g_off[dst + 1];
    __syncthreads();
    for (int base = beg; base < end; base += 128) {
        int n = min(128, end - base);
        if (t < n) epk[t] = g_pk[base + t];
        __syncthreads();
#pragma unroll 4
        for (int j = 0; j < n; ++j) {
            int p = epk[j];
            int src = p & 0xFFFF;
            int r = p >> 16;
            float w = x[src * GD + t] * inv_s[r];
#pragma unroll
            for (int rr = 0; rr < RR; ++rr) acc[rr] += (rr == r) ? w : 0.f;
        }
        __syncthreads();
    }
    float* ap = &g_agg[(size_t)dst * KCAT + t];
#pragma unroll
    for (int rr = 0; rr < RR; ++rr) ap[rr * GD] = acc[rr];
}

// ---------------- tf32 tensor-core GEMM, double-buffered ----------------
// blockIdx.y selects (B, bias, C) among up to 4 outputs sharing A.
// Optional second phase: + A2[M,K2] @ Broot (only with gridDim.y==1).

__device__ __forceinline__ uint32_t f2tf32(float f) {
    uint32_t r;
    asm("cvt.rna.tf32.f32 %0, %1;" : "=r"(r) : "f"(f));
    return r;
}

__global__ __launch_bounds__(256) void gemm_tf32(
    const float* __restrict__ A,
    const float* __restrict__ B0, const float* __restrict__ B1,
    const float* __restrict__ B2w, const float* __restrict__ B3,
    const float* __restrict__ b0, const float* __restrict__ b1,
    const float* __restrict__ b2, const float* __restrict__ b3,
    float* __restrict__ C0, float* __restrict__ C1,
    float* __restrict__ C2, float* __restrict__ C3,
    const float* __restrict__ A2, const float* __restrict__ Broot,
    int M, int K, int K2, int do_relu)
{
    __shared__ uint32_t As[2][128][20];
    __shared__ uint32_t Bs[2][16][136];   // 136 mod 32 = 8 -> conflict-free frag reads

    const float* Bsel; const float* bias; float* C;
    switch (blockIdx.y) {
        case 0:  Bsel = B0;  bias = b0; C = C0; break;
        case 1:  Bsel = B1;  bias = b1; C = C1; break;
        case 2:  Bsel = B2w; bias = b2; C = C2; break;
        default: Bsel = B3;  bias = b3; C = C3; break;
    }

    int tid = threadIdx.x;
    int m0 = blockIdx.x * 128;
    int warp = tid >> 5, lane = tid & 31;
    int wm = warp >> 1, wn = warp & 1;
    int grp = lane >> 2, tig = lane & 3;

    float c[2][8][4];
#pragma unroll
    for (int mi = 0; mi < 2; ++mi)
#pragma unroll
        for (int ni = 0; ni < 8; ++ni)
#pragma unroll
            for (int j = 0; j < 4; ++j) c[mi][ni][j] = 0.f;

    int a_row = tid >> 1;
    int a_kc  = (tid & 1) << 3;
    int b_row0 = tid >> 5;
    int b_col = (tid & 31) << 2;

    int t1 = K >> 4;
    int t2 = (A2 != nullptr) ? (K2 >> 4) : 0;
    int T = t1 + t2;

    float ar[8], br[8];

    auto ldg_tile = [&](int t) {
        const float* Ap; const float* Bt; int Kp; int kk;
        if (t < t1) { Ap = A;  Bt = Bsel;  Kp = K;  kk = t << 4; }
        else        { Ap = A2; Bt = Broot; Kp = K2; kk = (t - t1) << 4; }
        float4 v0 = make_float4(0.f, 0.f, 0.f, 0.f), v1 = v0;
        int row = m0 + a_row;
        if (row < M) {
            const float* p = &Ap[(size_t)row * Kp + kk + a_kc];
            v0 = *(const float4*)p;
            v1 = *(const float4*)(p + 4);
        }
        ar[0] = v0.x; ar[1] = v0.y; ar[2] = v0.z; ar[3] = v0.w;
        ar[4] = v1.x; ar[5] = v1.y; ar[6] = v1.z; ar[7] = v1.w;
        const float* bp = &Bt[(size_t)(kk + b_row0) * GD + b_col];
        float4 w0 = *(const float4*)bp;
        float4 w1 = *(const float4*)(bp + 8 * GD);
        br[0] = w0.x; br[1] = w0.y; br[2] = w0.z; br[3] = w0.w;
        br[4] = w1.x; br[5] = w1.y; br[6] = w1.z; br[7] = w1.w;
    };
    auto st_tile = [&](int buf) {
#pragma unroll
        for (int i = 0; i < 8; ++i) As[buf][a_row][a_kc + i] = f2tf32(ar[i]);
#pragma unroll
        for (int i = 0; i < 4; ++i) {
            Bs[buf][b_row0][b_col + i]     = f2tf32(br[i]);
            Bs[buf][b_row0 + 8][b_col + i] = f2tf32(br[4 + i]);
        }
    };

    ldg_tile(0);
    st_tile(0);
    __syncthreads();

    for (int t = 0; t < T; ++t) {
        int buf = t & 1;
        if (t + 1 < T) ldg_tile(t + 1);

#pragma unroll
        for (int ks = 0; ks < 2; ++ks) {
            int kk = ks << 3;
            uint32_t a[2][4];
#pragma unroll
            for (int mi = 0; mi < 2; ++mi) {
                int r0 = wm * 32 + mi * 16 + grp;
                a[mi][0] = As[buf][r0][kk + tig];
                a[mi][1] = As[buf][r0 + 8][kk + tig];
                a[mi][2] = As[buf][r0][kk + tig + 4];
                a[mi][3] = As[buf][r0 + 8][kk + tig + 4];
            }
            uint32_t b[8][2];
#pragma unroll
            for (int ni = 0; ni < 8; ++ni) {
                int n = wn * 64 + ni * 8 + grp;
                b[ni][0] = Bs[buf][kk + tig][n];
                b[ni][1] = Bs[buf][kk + tig + 4][n];
            }
#pragma unroll
            for (int mi = 0; mi < 2; ++mi)
#pragma unroll
                for (int ni = 0; ni < 8; ++ni) {
                    asm volatile(
                        "mma.sync.aligned.m16n8k8.row.col.f32.tf32.tf32.f32 "
                        "{%0,%1,%2,%3}, {%4,%5,%6,%7}, {%8,%9}, {%0,%1,%2,%3};"
                        : "+f"(c[mi][ni][0]), "+f"(c[mi][ni][1]),
                          "+f"(c[mi][ni][2]), "+f"(c[mi][ni][3])
                        : "r"(a[mi][0]), "r"(a[mi][1]), "r"(a[mi][2]), "r"(a[mi][3]),
                          "r"(b[ni][0]), "r"(b[ni][1]));
                }
        }

        if (t + 1 < T) st_tile(buf ^ 1);
        __syncthreads();
    }

#pragma unroll
    for (int mi = 0; mi < 2; ++mi) {
        int rbase = m0 + wm * 32 + mi * 16 + grp;
#pragma unroll
        for (int ni = 0; ni < 8; ++ni) {
            int col = wn * 64 + ni * 8 + 2 * tig;
            float2 bv = *(const float2*)&bias[col];
            if (rbase < M) {
                float2 o;
                o.x = c[mi][ni][0] + bv.x;
                o.y = c[mi][ni][1] + bv.y;
                if (do_relu) { o.x = fmaxf(o.x, 0.f); o.y = fmaxf(o.y, 0.f); }
                *(float2*)&C[(size_t)rbase * GD + col] = o;
            }
            if (rbase + 8 < M) {
                float2 o;
                o.x = c[mi][ni][2] + bv.x;
                o.y = c[mi][ni][3] + bv.y;
                if (do_relu) { o.x = fmaxf(o.x, 0.f); o.y = fmaxf(o.y, 0.f); }
                *(float2*)&C[(size_t)(rbase + 8) * GD + col] = o;
            }
        }
    }
}

// ---------------- fused attention: block per dst, online softmax, ILP-2 ----------------
__global__ __launch_bounds__(128) void attn_kernel(float* __restrict__ out) {
    __shared__ float qs[GD];
    __shared__ int epk[128];
    __shared__ float wm[4], ws[4];
    __shared__ float wacc[4][GD];
    int dst = blockIdx.x;
    int t = threadIdx.x;
    int w = t >> 5, lane = t & 31;

    qs[t] = g_q[dst * GD + t];
    int beg = g_off[dst], end = g_off[dst + 1];
    __syncthreads();
    float4 qv = ((float4*)qs)[lane];

    const float4* k4 = (const float4*)g_k;
    const float4* v4 = (const float4*)g_v;

    float m = -INFINITY, s = 0.f;
    float4 acc = make_float4(0.f, 0.f, 0.f, 0.f);

    for (int base = beg; base < end; base += 128) {
        int n = min(128, end - base);
        if (t < n) epk[t] = g_pk[base + t];
        __syncthreads();
        for (int j = w; j < n; j += 8) {
            int j2 = j + 4;
            bool has2 = j2 < n;
            int src1 = epk[j] & 0xFFFF;
            int src2 = epk[has2 ? j2 : j] & 0xFFFF;
            float4 kv1 = k4[src1 * 32 + lane];
            float4 kv2 = k4[src2 * 32 + lane];
            float p1 = qv.x * kv1.x + qv.y * kv1.y + qv.z * kv1.z + qv.w * kv1.w;
            float p2 = qv.x * kv2.x + qv.y * kv2.y + qv.z * kv2.z + qv.w * kv2.w;
#pragma unroll
            for (int o = 16; o; o >>= 1) {
                p1 += __shfl_xor_sync(0xffffffffu, p1, o);
                p2 += __shfl_xor_sync(0xffffffffu, p2, o);
            }
            p1 *= 0.08838834764831845f;
            p2 = has2 ? (p2 * 0.08838834764831845f) : -INFINITY;
            float4 vv1 = v4[src1 * 32 + lane];
            float4 vv2 = v4[src2 * 32 + lane];

            float mn = fmaxf(m, fmaxf(p1, p2));
            float scale = __expf(m - mn);          // m = -inf -> 0
            float e1 = __expf(p1 - mn);
            float e2 = has2 ? __expf(p2 - mn) : 0.f;
            s = s * scale + e1 + e2;
            acc.x = acc.x * scale + e1 * vv1.x + e2 * vv2.x;
            acc.y = acc.y * scale + e1 * vv1.y + e2 * vv2.y;
            acc.z = acc.z * scale + e1 * vv1.z + e2 * vv2.z;
            acc.w = acc.w * scale + e1 * vv1.w + e2 * vv2.w;
            m = mn;
        }
        __syncthreads();
    }

    if (lane == 0) { wm[w] = m; ws[w] = s; }
    ((float4*)wacc[w])[lane] = acc;
    __syncthreads();

    float M = fmaxf(fmaxf(wm[0], wm[1]), fmaxf(wm[2], wm[3]));
    float stot = 0.f, val = 0.f;
#pragma unroll
    for (int w2 = 0; w2 < 4; ++w2) {
        float sw = ws[w2];
        if (sw > 0.f) {
            float sc = __expf(wm[w2] - M);
            stot += sw * sc;
            val += wacc[w2][t] * sc;
        }
    }
    float res = (stot > 0.f) ? (val / stot) : 0.f;
    float o = out[dst * GD + t] + res;
    out[dst * GD + t] = fmaxf(o, 0.f);
}

// ---------------- launch ----------------
extern "C" void kernel_launch(void* const* d_in, const int* in_sizes, int n_in,
                              void* d_out, int out_size) {
    const float* x     = (const float*)d_in[0];
    const int*   ei    = (const int*)d_in[1];
    const int*   et    = (const int*)d_in[2];
    const float* rw    = (const float*)d_in[3];
    const float* rroot = (const float*)d_in[4];
    const float* rbias = (const float*)d_in[5];
    const float* Wq    = (const float*)d_in[6];
    const float* bq    = (const float*)d_in[7];
    const float* Wk    = (const float*)d_in[8];
    const float* bk    = (const float*)d_in[9];
    const float* Wv    = (const float*)d_in[10];
    const float* bv    = (const float*)d_in[11];
    const float* Ws    = (const float*)d_in[12];
    const float* bs    = (const float*)d_in[13];
    float* out = (float*)d_out;

    const int threads = 256;
    const int eqBlocks = (E_EDGES / 4 + threads - 1) / threads;   // 625
    const int mBlocks = (N_NODES + 127) / 128;                    // 157

    float* d_h; cudaGetSymbolAddress((void**)&d_h, g_h);
    float* d_q; cudaGetSymbolAddress((void**)&d_q, g_q);
    float* d_k; cudaGetSymbolAddress((void**)&d_k, g_k);
    float* d_v; cudaGetSymbolAddress((void**)&d_v, g_v);
    float* d_agg; cudaGetSymbolAddress((void**)&d_agg, g_agg);

    // CSR build
    zero_ints<<<160, threads>>>();
    count_kernel<<<eqBlocks, threads>>>(ei, et);
    scan_kernel<<<1, 1024>>>();
    scatter_kernel<<<eqBlocks, threads>>>(ei, et);

    // RGCN: aggregate, then fused big GEMM (agg@Wcat + x@root) + relu
    rgcn_agg<<<N_NODES, 128>>>(x);
    gemm_tf32<<<dim3(mBlocks, 1), threads>>>(
        d_agg, rw, rw, rw, rw, rbias, rbias, rbias, rbias,
        d_h, d_h, d_h, d_h, x, rroot, N_NODES, KCAT, GD, 1);

    // q, k, v, skip(->out) fused: 4 outputs share A = g_h
    gemm_tf32<<<dim3(mBlocks, 4), threads>>>(
        d_h, Wq, Wk, Wv, Ws, bq, bk, bv, bs,
        d_q, d_k, d_v, out, nullptr, nullptr, N_NODES, GD, 0, 0);

    // fused attention + skip + relu
    attn_kernel<<<N_NODES, 128>>>(out);
}